// round 1
// baseline (speedup 1.0000x reference)
#include <cuda_runtime.h>
#include <math.h>

#define NEG_INF (-1e9f)
#define MAXSEG 257          // <=256 interior breakpoints + 1
#define MAXP   (8*256*256)  // B*N*N
#define NB1MAX (MAXP/256)
#define NB2    256

// ---------------- scratch (device globals: allowed) ----------------
__device__ float  d_t[MAXSEG + 1];      // segment boundaries: 0, bp..., 1
__device__ int    d_nseg;
__device__ float4 d_puvw[MAXSEG * 128]; // {u, v, W2b[i], 0} per segment
__device__ float  d_r3[MAXSEG * 256];   // slope  of h3 pre-act
__device__ float  d_s3[MAXSEG * 256];   // offset of h3 pre-act
__device__ float  d_logits[MAXP];
__device__ float  d_bmax[NB1MAX];
__device__ float  d_gmax;
__device__ float  d_Hpart[NB2 * 256];
__device__ float  d_Zpart[NB2];

// ---------------- K1: find + sort layer-1 breakpoints in (0,1) ----------------
__global__ void k_breakpoints(const float* __restrict__ W1a,
                              const float* __restrict__ b1a) {
    __shared__ float s[256];
    __shared__ int cnt;
    int tid = threadIdx.x;
    if (tid == 0) cnt = 0;
    __syncthreads();
    float a = W1a[tid], b = b1a[tid];
    if (a != 0.0f) {
        float t = -b / a;
        if (t > 0.0f && t < 1.0f) {
            int pos = atomicAdd(&cnt, 1);
            s[pos] = t;
        }
    }
    __syncthreads();
    int n = cnt;
    if (tid >= n) s[tid] = 2.0f;   // pad sorts to the end
    __syncthreads();
    // bitonic sort, 256 elements / 256 threads
    for (int k = 2; k <= 256; k <<= 1) {
        for (int j = k >> 1; j > 0; j >>= 1) {
            int ixj = tid ^ j;
            if (ixj > tid) {
                float x = s[tid], y = s[ixj];
                bool up = ((tid & k) == 0);
                if ((x > y) == up) { s[tid] = y; s[ixj] = x; }
            }
            __syncthreads();
        }
    }
    if (tid < n) d_t[tid + 1] = s[tid];
    if (tid == 0) {
        d_t[0]     = 0.0f;
        d_t[n + 1] = 1.0f;
        d_nseg     = n + 1;
    }
}

// ---------------- K2: per-segment linearization tables ----------------
// For each segment: emb(e) = e*C + D (C,D in R^128), then
//   u = C@W2a, v = D@W2a + b2a   (logit path)
//   r = C@W3a, s = D@W3a + b3a   (value path)
__global__ void k_tables(const float* __restrict__ W1a, const float* __restrict__ b1a,
                         const float* __restrict__ W1b, const float* __restrict__ b1b,
                         const float* __restrict__ W2a, const float* __restrict__ b2a,
                         const float* __restrict__ W2b,
                         const float* __restrict__ W3a, const float* __restrict__ b3a) {
    int seg = blockIdx.x;
    if (seg >= d_nseg) return;
    int tid = threadIdx.x;  // 128 threads
    __shared__ float Cs[128], Ds[128];
    float emid = 0.5f * (d_t[seg] + d_t[seg + 1]);

    float c = 0.0f, dd = 0.0f;
    for (int j = 0; j < 256; j++) {
        float a = __ldg(W1a + j), b = __ldg(b1a + j);
        if (fmaf(a, emid, b) > 0.0f) {   // sign constant within the segment
            float w = __ldg(W1b + j * 128 + tid);
            c  = fmaf(a, w, c);
            dd = fmaf(b, w, dd);
        }
    }
    dd += __ldg(b1b + tid);
    Cs[tid] = c; Ds[tid] = dd;
    __syncthreads();

    // logit path
    float u = 0.0f, v = __ldg(b2a + tid);
    for (int k = 0; k < 128; k++) {
        float w = __ldg(W2a + k * 128 + tid);
        u = fmaf(Cs[k], w, u);
        v = fmaf(Ds[k], w, v);
    }
    d_puvw[seg * 128 + tid] = make_float4(u, v, __ldg(W2b + tid), 0.0f);

    // value path (256 dims, 2 per thread)
    for (int h = 0; h < 2; h++) {
        int dim = tid + h * 128;
        float r = 0.0f, sv = __ldg(b3a + dim);
        for (int k = 0; k < 128; k++) {
            float w = __ldg(W3a + k * 256 + dim);
            r  = fmaf(Cs[k], w, r);
            sv = fmaf(Ds[k], w, sv);
        }
        d_r3[seg * 256 + dim] = r;
        d_s3[seg * 256 + dim] = sv;
    }
}

__device__ __forceinline__ int find_seg(float e, int nseg) {
    int lo = 0, hi = nseg - 1;
    while (lo < hi) {
        int mid = (lo + hi) >> 1;
        if (e < __ldg(&d_t[mid + 1])) hi = mid; else lo = mid + 1;
    }
    return lo;
}

// ---------------- K3: pass 1 — per-edge logit + block max ----------------
__global__ void k_pass1(const float* __restrict__ adj,
                        const float* __restrict__ b2b, int P) {
    int p = blockIdx.x * blockDim.x + threadIdx.x;
    float logit = NEG_INF;
    int nseg = d_nseg;
    if (p < P) {
        float e = __ldg(adj + p);
        if (e > 0.0f && e < 1.0f) {
            int seg = find_seg(e, nseg);
            const float4* q = d_puvw + seg * 128;
            float acc = __ldg(b2b);
            #pragma unroll 4
            for (int i = 0; i < 128; i++) {
                float4 t = __ldg(q + i);                 // broadcast LDG.128
                float h = fmaxf(fmaf(e, t.x, t.y), 0.0f);
                acc = fmaf(h, t.z, acc);
            }
            logit = acc;
        }
        d_logits[p] = logit;
    }
    __shared__ float sm[256];
    sm[threadIdx.x] = logit;
    __syncthreads();
    for (int s = 128; s > 0; s >>= 1) {
        if (threadIdx.x < s) sm[threadIdx.x] = fmaxf(sm[threadIdx.x], sm[threadIdx.x + s]);
        __syncthreads();
    }
    if (threadIdx.x == 0) d_bmax[blockIdx.x] = sm[0];
}

// ---------------- K4: global max reduce ----------------
__global__ void k_maxreduce(int nb) {
    __shared__ float sm[256];
    float m = NEG_INF;
    for (int i = threadIdx.x; i < nb; i += 256) m = fmaxf(m, d_bmax[i]);
    sm[threadIdx.x] = m;
    __syncthreads();
    for (int s = 128; s > 0; s >>= 1) {
        if (threadIdx.x < s) sm[threadIdx.x] = fmaxf(sm[threadIdx.x], sm[threadIdx.x + s]);
        __syncthreads();
    }
    if (threadIdx.x == 0) d_gmax = sm[0];
}

// ---------------- K5: pass 2 — warp-cooperative alpha-weighted h3 sum ----------------
// Each warp owns a contiguous edge range; all 32 lanes work on the SAME edge,
// lane L accumulates dims {L, L+32, ..., L+224}. seg is warp-uniform so the
// per-segment r/s tables live in registers, reloaded only on segment change.
__global__ void k_pass2(const float* __restrict__ adj, int P) {
    int warp = threadIdx.x >> 5, lane = threadIdx.x & 31;
    int gw = blockIdx.x * 8 + warp;
    int nwarps = gridDim.x * 8;
    int per = (P + nwarps - 1) / nwarps;
    int p0 = gw * per;
    int p1 = min(p0 + per, P);
    float gmax = d_gmax;
    int nseg = d_nseg;

    float acc[8], r[8], s[8];
    #pragma unroll
    for (int k = 0; k < 8; k++) acc[k] = 0.0f;
    int cur = -1;
    float zacc = 0.0f;

    for (int p = p0; p < p1; p++) {
        float e = __ldg(adj + p);                 // broadcast
        if (!(e > 0.0f && e < 1.0f)) continue;    // warp-uniform skip
        float w = expf(__ldg(&d_logits[p]) - gmax);
        int seg = find_seg(e, nseg);
        if (seg != cur) {                         // warp-uniform, rare
            cur = seg;
            #pragma unroll
            for (int k = 0; k < 8; k++) {
                r[k] = __ldg(&d_r3[seg * 256 + lane + 32 * k]);
                s[k] = __ldg(&d_s3[seg * 256 + lane + 32 * k]);
            }
        }
        zacc += w;
        #pragma unroll
        for (int k = 0; k < 8; k++) {
            float h = fmaxf(fmaf(e, r[k], s[k]), 0.0f);
            acc[k] = fmaf(w, h, acc[k]);
        }
    }

    __shared__ float Hs[8][256];
    __shared__ float Zs[8];
    #pragma unroll
    for (int k = 0; k < 8; k++) Hs[warp][lane + 32 * k] = acc[k];
    if (lane == 0) Zs[warp] = zacc;
    __syncthreads();
    int d = threadIdx.x;
    float hsum = 0.0f;
    #pragma unroll
    for (int wq = 0; wq < 8; wq++) hsum += Hs[wq][d];
    d_Hpart[blockIdx.x * 256 + d] = hsum;
    if (d == 0) {
        float z = 0.0f;
        #pragma unroll
        for (int wq = 0; wq < 8; wq++) z += Zs[wq];
        d_Zpart[blockIdx.x] = z;
    }
}

// ---------------- K6: final reduce + W3b + fc4 head ----------------
__global__ void k_final(const float* __restrict__ W3b, const float* __restrict__ b3b,
                        const float* __restrict__ W4a, const float* __restrict__ b4a,
                        const float* __restrict__ W4b, const float* __restrict__ b4b,
                        float* __restrict__ out, int nb2) {
    __shared__ float Hn[256], Wt[128], H4[256];
    __shared__ float sInvZ, sS0;
    int tid = threadIdx.x;

    float h = 0.0f;
    for (int b = 0; b < nb2; b++) h += d_Hpart[b * 256 + tid];
    if (tid == 0) {
        float z = 0.0f;
        for (int b = 0; b < nb2; b++) z += d_Zpart[b];
        sInvZ = (z > 0.0f) ? (1.0f / z) : 0.0f;
        sS0   = (z > 0.0f) ? 1.0f : 0.0f;
    }
    __syncthreads();
    Hn[tid] = h * sInvZ;
    __syncthreads();

    if (tid < 128) {   // weighted = (H/Z) @ W3b + S0*b3b
        float acc = sS0 * __ldg(b3b + tid);
        for (int d = 0; d < 256; d++)
            acc = fmaf(Hn[d], __ldg(W3b + d * 128 + tid), acc);
        Wt[tid] = acc;
    }
    __syncthreads();
    {   // h4 = relu(weighted @ W4a + b4a)
        float acc = __ldg(b4a + tid);
        for (int m = 0; m < 128; m++)
            acc = fmaf(Wt[m], __ldg(W4a + m * 256 + tid), acc);
        H4[tid] = fmaxf(acc, 0.0f);
    }
    __syncthreads();
    if (tid < 64) {  // out = h4 @ W4b + b4b
        float acc = __ldg(b4b + tid);
        for (int n = 0; n < 256; n++)
            acc = fmaf(H4[n], __ldg(W4b + n * 64 + tid), acc);
        out[tid] = acc;
    }
}

// ---------------- launch ----------------
extern "C" void kernel_launch(void* const* d_in, const int* in_sizes, int n_in,
                              void* d_out, int out_size) {
    const float* adj = (const float*)d_in[1];
    const float* W1a = (const float*)d_in[3];
    const float* b1a = (const float*)d_in[4];
    const float* W1b = (const float*)d_in[5];
    const float* b1b = (const float*)d_in[6];
    const float* W2a = (const float*)d_in[7];
    const float* b2a = (const float*)d_in[8];
    const float* W2b = (const float*)d_in[9];
    const float* b2b = (const float*)d_in[10];
    const float* W3a = (const float*)d_in[11];
    const float* b3a = (const float*)d_in[12];
    const float* W3b = (const float*)d_in[13];
    const float* b3b = (const float*)d_in[14];
    const float* W4a = (const float*)d_in[15];
    const float* b4a = (const float*)d_in[16];
    const float* W4b = (const float*)d_in[17];
    const float* b4b = (const float*)d_in[18];

    int P = in_sizes[1];
    int nb1 = (P + 255) / 256;

    k_breakpoints<<<1, 256>>>(W1a, b1a);
    k_tables<<<MAXSEG, 128>>>(W1a, b1a, W1b, b1b, W2a, b2a, W2b, W3a, b3a);
    k_pass1<<<nb1, 256>>>(adj, b2b, P);
    k_maxreduce<<<1, 256>>>(nb1);
    k_pass2<<<NB2, 256>>>(adj, P);
    k_final<<<1, 256>>>(W3b, b3b, W4a, b4a, W4b, b4b, (float*)d_out, NB2);
}

// round 2
// speedup vs baseline: 1.0322x; 1.0322x over previous
#include <cuda_runtime.h>
#include <math.h>

#define NEG_INF (-1e9f)
#define MAXSEG1 257          // layer-1 segments (<=256 breakpoints + 1)
#define REFCAP  2048         // refined boundary capacity (power of 2)
#define LUTN    4096

// ---------------- scratch ----------------
__device__ float    d_t[MAXSEG1 + 1];       // layer-1 boundaries 0..1
__device__ int      d_nseg;                 // layer-1 segment count
__device__ float4   d_uvw[MAXSEG1 * 128];   // {u, v, W2b[i], 0} per L1 seg
__device__ float    d_r3[MAXSEG1 * 256];    // value-path slope (pre-relu)
__device__ float    d_s3[MAXSEG1 * 256];    // value-path offset
__device__ float    d_tr[REFCAP];           // refined boundaries (sorted)
__device__ int      d_nref;                 // refined segment count
__device__ unsigned short d_lut[LUTN];      // bucket -> refined seg hint
__device__ float2   d_AB[REFCAP];           // logit affine per refined seg
__device__ float    d_R[REFCAP * 256];      // post-relu value slope
__device__ float    d_S[REFCAP * 256];      // post-relu value offset
__device__ unsigned d_gmaxint;              // encoded domain max of logit
__device__ float    d_binW[REFCAP];         // sum of alpha-weights per seg
__device__ float    d_binWE[REFCAP];        // sum of w*e per seg

__device__ __forceinline__ unsigned fenc(float f) {
    int i = __float_as_int(f);
    return (i >= 0) ? ((unsigned)i | 0x80000000u) : ~((unsigned)i);
}
__device__ __forceinline__ float fdec(unsigned u) {
    int i = (u & 0x80000000u) ? (int)(u & 0x7fffffffu) : ~(int)u;
    return __int_as_float(i);
}

// ---------------- K1: layer-1 breakpoints in (0,1), sorted ----------------
__global__ void k_breakpoints(const float* __restrict__ W1a,
                              const float* __restrict__ b1a) {
    __shared__ float s[256];
    __shared__ int cnt;
    int tid = threadIdx.x;
    if (tid == 0) { cnt = 0; d_gmaxint = fenc(-1e30f); }
    __syncthreads();
    float a = W1a[tid], b = b1a[tid];
    if (a != 0.0f) {
        float t = -b / a;
        if (t > 0.0f && t < 1.0f) s[atomicAdd(&cnt, 1)] = t;
    }
    __syncthreads();
    int n = cnt;
    if (tid >= n) s[tid] = 2.0f;
    __syncthreads();
    for (int k = 2; k <= 256; k <<= 1)
        for (int j = k >> 1; j > 0; j >>= 1) {
            int ixj = tid ^ j;
            if (ixj > tid) {
                float x = s[tid], y = s[ixj];
                bool up = ((tid & k) == 0);
                if ((x > y) == up) { s[tid] = y; s[ixj] = x; }
            }
            __syncthreads();
        }
    if (tid < n) d_t[tid + 1] = s[tid];
    if (tid == 0) { d_t[0] = 0.0f; d_t[n + 1] = 1.0f; d_nseg = n + 1; }
}

// ---------------- K2: per layer-1 segment linearization ----------------
__global__ void k_tables(const float* __restrict__ W1a, const float* __restrict__ b1a,
                         const float* __restrict__ W1b, const float* __restrict__ b1b,
                         const float* __restrict__ W2a, const float* __restrict__ b2a,
                         const float* __restrict__ W2b,
                         const float* __restrict__ W3a, const float* __restrict__ b3a) {
    int seg = blockIdx.x;
    if (seg >= d_nseg) return;
    int tid = threadIdx.x;  // 128 threads
    __shared__ float Cs[128], Ds[128];
    float emid = 0.5f * (d_t[seg] + d_t[seg + 1]);

    float c = 0.0f, dd = 0.0f;
    #pragma unroll 4
    for (int j = 0; j < 256; j++) {
        float a = __ldg(W1a + j), b = __ldg(b1a + j);
        if (fmaf(a, emid, b) > 0.0f) {
            float w = __ldg(W1b + j * 128 + tid);
            c  = fmaf(a, w, c);
            dd = fmaf(b, w, dd);
        }
    }
    dd += __ldg(b1b + tid);
    Cs[tid] = c; Ds[tid] = dd;
    __syncthreads();

    float u = 0.0f, v = __ldg(b2a + tid);
    #pragma unroll 4
    for (int k = 0; k < 128; k++) {
        float w = __ldg(W2a + k * 128 + tid);
        u = fmaf(Cs[k], w, u);
        v = fmaf(Ds[k], w, v);
    }
    d_uvw[seg * 128 + tid] = make_float4(u, v, __ldg(W2b + tid), 0.0f);

    #pragma unroll
    for (int h = 0; h < 2; h++) {
        int dim = tid + h * 128;
        float r = 0.0f, sv = __ldg(b3a + dim);
        #pragma unroll 4
        for (int k = 0; k < 128; k++) {
            float w = __ldg(W3a + k * 256 + dim);
            r  = fmaf(Cs[k], w, r);
            sv = fmaf(Ds[k], w, sv);
        }
        d_r3[seg * 256 + dim] = r;
        d_s3[seg * 256 + dim] = sv;
    }
}

// ---------------- K3: refined breakpoints (L1 + L2 roots), sort, LUT ----------------
__global__ void k_refine() {
    __shared__ float sv[REFCAP];
    __shared__ int cnt;
    int tid = threadIdx.x;  // 1024
    if (tid == 0) cnt = 0;
    for (int i = tid; i < REFCAP; i += 1024) sv[i] = 2.0f;
    __syncthreads();

    int nseg1 = d_nseg;
    int total = nseg1 * 384;
    for (int idx = tid; idx < total; idx += 1024) {
        int seg1 = idx / 384, k = idx % 384;
        float lo = d_t[seg1], hi = d_t[seg1 + 1];
        float a, b;
        if (k < 128) { float4 q = d_uvw[seg1 * 128 + k]; a = q.x; b = q.y; }
        else { int dm = k - 128; a = d_r3[seg1 * 256 + dm]; b = d_s3[seg1 * 256 + dm]; }
        if (a != 0.0f) {
            float t = -b / a;
            if (t > lo && t < hi) {
                int pos = atomicAdd(&cnt, 1);
                if (pos < REFCAP) sv[pos] = t;
            }
        }
    }
    for (int i = tid; i <= nseg1; i += 1024) {
        int pos = atomicAdd(&cnt, 1);
        if (pos < REFCAP) sv[pos] = d_t[i];
    }
    __syncthreads();
    int n = min(cnt, REFCAP);
    __syncthreads();

    // bitonic sort, REFCAP elems / 1024 threads
    for (int k = 2; k <= REFCAP; k <<= 1)
        for (int j = k >> 1; j > 0; j >>= 1) {
            for (int i = tid; i < REFCAP; i += 1024) {
                int ixj = i ^ j;
                if (ixj > i) {
                    float x = sv[i], y = sv[ixj];
                    bool up = ((i & k) == 0);
                    if ((x > y) == up) { sv[i] = y; sv[ixj] = x; }
                }
            }
            __syncthreads();
        }

    int nref = n - 1;
    if (tid == 0) d_nref = nref;
    for (int i = tid; i < n; i += 1024) d_tr[i] = sv[i];
    // LUT: segment containing each bucket's lower edge
    for (int b = tid; b < LUTN; b += 1024) {
        float e = (float)b * (1.0f / LUTN);
        int lo = 0, hi = nref - 1;
        while (lo < hi) {
            int mid = (lo + hi + 1) >> 1;
            if (sv[mid] <= e) lo = mid; else hi = mid - 1;
        }
        d_lut[b] = (unsigned short)lo;
    }
}

// ---------------- K4: per refined segment: affine logit, masked value tables ----------------
__global__ void k_segtab(const float* __restrict__ b2b) {
    int rs = blockIdx.x;
    if (rs >= d_nref) return;
    int tid = threadIdx.x;  // 256
    float lo = d_tr[rs], hi = d_tr[rs + 1];
    float emid = 0.5f * (lo + hi);

    int nseg1 = d_nseg;
    int l = 0, h = nseg1 - 1;
    while (l < h) { int m = (l + h + 1) >> 1; if (d_t[m] <= emid) l = m; else h = m - 1; }
    int p = l;

    __shared__ float sA[128], sB[128];
    if (tid < 128) {
        float4 q = d_uvw[p * 128 + tid];
        bool act = fmaf(q.x, emid, q.y) > 0.0f;
        sA[tid] = act ? q.x * q.z : 0.0f;
        sB[tid] = act ? q.y * q.z : 0.0f;
    }
    __syncthreads();
    for (int s = 64; s > 0; s >>= 1) {
        if (tid < s) { sA[tid] += sA[tid + s]; sB[tid] += sB[tid + s]; }
        __syncthreads();
    }
    if (tid == 0) {
        float A = sA[0], B = sB[0] + __ldg(b2b);
        d_AB[rs] = make_float2(A, B);
        float m = fmaxf(fmaf(A, lo, B), fmaf(A, hi, B));
        atomicMax(&d_gmaxint, fenc(m));
        d_binW[rs] = 0.0f; d_binWE[rs] = 0.0f;
    }
    {
        float r = d_r3[p * 256 + tid], s = d_s3[p * 256 + tid];
        bool act = fmaf(r, emid, s) > 0.0f;
        d_R[rs * 256 + tid] = act ? r : 0.0f;
        d_S[rs * 256 + tid] = act ? s : 0.0f;
    }
}

// ---------------- K5: single edge pass — O(1) per edge ----------------
__global__ void k_edges(const float* __restrict__ adj, int P) {
    __shared__ float s_tr[REFCAP];
    __shared__ unsigned short s_lut[LUTN];
    __shared__ float s_W[REFCAP], s_WE[REFCAP];
    int nref = d_nref;
    int tid = threadIdx.x;
    for (int i = tid; i <= nref; i += 256) s_tr[i] = d_tr[i];
    for (int i = tid; i < LUTN; i += 256) s_lut[i] = d_lut[i];
    for (int i = tid; i < nref; i += 256) { s_W[i] = 0.0f; s_WE[i] = 0.0f; }
    __syncthreads();
    float gmax = fdec(d_gmaxint);

    int stride = gridDim.x * blockDim.x;
    for (int pi = blockIdx.x * blockDim.x + tid; pi < P; pi += stride) {
        float e = __ldg(adj + pi);
        if (e > 0.0f && e < 1.0f) {
            int b = min((int)(e * (float)LUTN), LUTN - 1);
            int seg = s_lut[b];
            while (seg + 1 < nref && e >= s_tr[seg + 1]) seg++;
            while (seg > 0 && e < s_tr[seg]) seg--;
            float2 ab = __ldg(&d_AB[seg]);
            float w = __expf(fmaf(ab.x, e, ab.y) - gmax);
            atomicAdd(&s_W[seg], w);
            atomicAdd(&s_WE[seg], w * e);
        }
    }
    __syncthreads();
    for (int i = tid; i < nref; i += 256) {
        float w = s_W[i];
        if (w != 0.0f) {
            atomicAdd(&d_binW[i], w);
            atomicAdd(&d_binWE[i], s_WE[i]);
        }
    }
}

// ---------------- K6: combine bins -> H, then W3b + fc4 head ----------------
__global__ void k_final(const float* __restrict__ W3b, const float* __restrict__ b3b,
                        const float* __restrict__ W4a, const float* __restrict__ b4a,
                        const float* __restrict__ W4b, const float* __restrict__ b4b,
                        float* __restrict__ out) {
    __shared__ float sW[REFCAP], sWE[REFCAP];
    __shared__ float Hn[256], Wt[128], H4[256], red[256];
    __shared__ float sInvZ, sS0;
    int tid = threadIdx.x;  // 256
    int nref = d_nref;
    for (int i = tid; i < nref; i += 256) { sW[i] = d_binW[i]; sWE[i] = d_binWE[i]; }
    __syncthreads();

    // H[d] = sum_rs WE*R + W*S   (coalesced over d=tid)
    float acc = 0.0f;
    for (int rs = 0; rs < nref; rs++)
        acc = fmaf(sWE[rs], __ldg(&d_R[rs * 256 + tid]),
              fmaf(sW[rs],  __ldg(&d_S[rs * 256 + tid]), acc));

    // Z = sum W (parallel reduce)
    float z = 0.0f;
    for (int i = tid; i < nref; i += 256) z += sW[i];
    red[tid] = z;
    __syncthreads();
    for (int s = 128; s > 0; s >>= 1) {
        if (tid < s) red[tid] += red[tid + s];
        __syncthreads();
    }
    if (tid == 0) {
        float Z = red[0];
        sInvZ = (Z > 0.0f) ? (1.0f / Z) : 0.0f;
        sS0   = (Z > 0.0f) ? 1.0f : 0.0f;
    }
    __syncthreads();
    Hn[tid] = acc * sInvZ;
    __syncthreads();

    if (tid < 128) {   // weighted = Hn @ W3b + b3b
        float a2 = sS0 * __ldg(b3b + tid);
        #pragma unroll 4
        for (int d = 0; d < 256; d++)
            a2 = fmaf(Hn[d], __ldg(W3b + d * 128 + tid), a2);
        Wt[tid] = a2;
    }
    __syncthreads();
    {   // h4 = relu(weighted @ W4a + b4a)
        float a3 = __ldg(b4a + tid);
        #pragma unroll 4
        for (int m = 0; m < 128; m++)
            a3 = fmaf(Wt[m], __ldg(W4a + m * 256 + tid), a3);
        H4[tid] = fmaxf(a3, 0.0f);
    }
    __syncthreads();
    if (tid < 64) {    // out = h4 @ W4b + b4b
        float a4 = __ldg(b4b + tid);
        #pragma unroll 4
        for (int n = 0; n < 256; n++)
            a4 = fmaf(H4[n], __ldg(W4b + n * 64 + tid), a4);
        out[tid] = a4;
    }
}

// ---------------- launch ----------------
extern "C" void kernel_launch(void* const* d_in, const int* in_sizes, int n_in,
                              void* d_out, int out_size) {
    const float* adj = (const float*)d_in[1];
    const float* W1a = (const float*)d_in[3];
    const float* b1a = (const float*)d_in[4];
    const float* W1b = (const float*)d_in[5];
    const float* b1b = (const float*)d_in[6];
    const float* W2a = (const float*)d_in[7];
    const float* b2a = (const float*)d_in[8];
    const float* W2b = (const float*)d_in[9];
    const float* b2b = (const float*)d_in[10];
    const float* W3a = (const float*)d_in[11];
    const float* b3a = (const float*)d_in[12];
    const float* W3b = (const float*)d_in[13];
    const float* b3b = (const float*)d_in[14];
    const float* W4a = (const float*)d_in[15];
    const float* b4a = (const float*)d_in[16];
    const float* W4b = (const float*)d_in[17];
    const float* b4b = (const float*)d_in[18];

    int P = in_sizes[1];

    k_breakpoints<<<1, 256>>>(W1a, b1a);
    k_tables<<<MAXSEG1, 128>>>(W1a, b1a, W1b, b1b, W2a, b2a, W2b, W3a, b3a);
    k_refine<<<1, 1024>>>();
    k_segtab<<<REFCAP, 256>>>(b2b);
    k_edges<<<296, 256>>>(adj, P);
    k_final<<<1, 256>>>(W3b, b3b, W4a, b4a, W4b, b4b, (float*)d_out);
}